// round 2
// baseline (speedup 1.0000x reference)
#include <cuda_runtime.h>

#define B_   256
#define T_   1024
#define NUM_ 126
#define L_   128

__device__ int d_perm[B_];

// Rank-sort sequences by length (descending), deterministic, O(n^2) with n=256.
__global__ void crf_sort_kernel(const int* __restrict__ lens){
    __shared__ int sl[B_];
    int i = threadIdx.x;
    sl[i] = lens[i];
    __syncthreads();
    int v = sl[i];
    int r = 0;
    #pragma unroll 8
    for (int j = 0; j < B_; j++){
        int w = sl[j];
        r += (int)((w > v) | ((w == v) & (j < i)));
    }
    d_perm[r] = i;
}

__device__ __forceinline__ void ffma2(unsigned long long &d, unsigned long long a, unsigned long long b){
    asm volatile("fma.rn.f32x2 %0, %1, %2, %0;" : "+l"(d) : "l"(a), "l"(b));
}
__device__ __forceinline__ unsigned long long fadd2(unsigned long long a, unsigned long long b){
    unsigned long long d;
    asm volatile("add.rn.f32x2 %0, %1, %2;" : "=l"(d) : "l"(a), "l"(b));
    return d;
}

// Half-row dot: s = sum_{i<64} E[i]*p[i]; E is 32 packed f32x2 regs, p broadcast from smem.
__device__ __forceinline__ float dot64(const float* __restrict__ p, const unsigned long long* __restrict__ E){
    const ulonglong2* pd = (const ulonglong2*)p;   // 16 entries x 16B
    unsigned long long a0 = 0ull, a1 = 0ull, a2 = 0ull, a3 = 0ull;
    #pragma unroll
    for (int i = 0; i < 16; i += 2){
        ulonglong2 q0 = pd[i];
        ulonglong2 q1 = pd[i + 1];
        ffma2(a0, E[2*i + 0], q0.x);
        ffma2(a1, E[2*i + 1], q0.y);
        ffma2(a2, E[2*i + 2], q1.x);
        ffma2(a3, E[2*i + 3], q1.y);
    }
    unsigned long long s2 = fadd2(fadd2(a0, a1), fadd2(a2, a3));
    return __uint_as_float((unsigned)(s2 & 0xffffffffull)) +
           __uint_as_float((unsigned)(s2 >> 32));
}

#define GBAR(id) asm volatile("bar.sync %0, 256;" :: "r"(id) : "memory")

__global__ void __launch_bounds__(512, 1)
crf_main_kernel(const float* __restrict__ logits,
                const int*   __restrict__ labels,
                const int*   __restrict__ lens,
                const float* __restrict__ trans,
                float*       __restrict__ out)
{
    __shared__ __align__(16) float pbuf_all[2][2][L_];
    __shared__ __align__(16) float red_all[2][16];

    const int tid   = threadIdx.x;
    const int grp   = tid >> 8;            // 0/1: two independent sequence groups
    const int gt    = tid & 255;           // thread index inside group
    const int label = gt >> 1;             // label owned by this lane pair
    const int half  = gt & 1;              // 0: i in [0,64), 1: i in [64,128)
    const int lane  = tid & 31;
    const int wrp   = gt >> 5;             // warp index within group (0..7)
    const int barid = 1 + grp;

    const int rank = (grp == 0) ? (int)blockIdx.x : (B_ - 1 - (int)blockIdx.x);
    const int seq  = d_perm[rank];
    const int len  = lens[seq];

    float (*pb)[L_] = pbuf_all[grp];
    float* red      = red_all[grp];

    // ---- E half-row (exp of transition row `label`, columns half*64..) in 32 f32x2 regs ----
    unsigned long long Ereg[32];
    {
        const float* trow = trans + label * L_ + half * 64;
        #pragma unroll
        for (int m = 0; m < 32; m++){
            float e0 = expf(trow[2*m]);
            float e1 = expf(trow[2*m + 1]);
            Ereg[m] = (unsigned long long)__float_as_uint(e0)
                    | ((unsigned long long)__float_as_uint(e1) << 32);
        }
    }

    const float* lgp = logits + (size_t)seq * T_ * NUM_;

    // ---- gold score partial (group threads stride over time) ----
    float gpart = 0.f;
    {
        const int* lab = labels + seq * T_;
        for (int t = gt; t < len; t += 256){
            int l1 = lab[t];
            gpart += lgp[(size_t)t * NUM_ + l1];
            int l0 = (t == 0) ? (L_ - 2) : lab[t - 1];
            gpart += trans[l1 * L_ + l0];
        }
        if (gt == 0) gpart += trans[(L_ - 1) * L_ + lab[len - 1]];
    }

    // ---- init p0 ----
    if (!half) pb[0][label] = (label == (L_ - 2)) ? 1.f : 0.f;
    GBAR(barid);

    const bool lab_ok = (label < NUM_);
    float lgbuf[4];
    #pragma unroll
    for (int k = 0; k < 4; k++)
        lgbuf[k] = lab_ok ? __ldg(lgp + (size_t)k * NUM_ + label) : -1.0e30f;

    float c    = 0.f;   // accumulated log-scale
    float pend = 1.f;   // pending 1/m from last renormalization
    int   t0   = 0;

    // ---- main scan: blocks of 4 steps, renorm every 4th step, prefetch 4 ahead ----
    while (t0 + 4 <= len){
        float nbuf[4];
        #pragma unroll
        for (int k = 0; k < 4; k++){
            int tp = t0 + 4 + k;
            nbuf[k] = (lab_ok && tp < T_) ? __ldg(lgp + (size_t)tp * NUM_ + label) : -1.0e30f;
        }
        #pragma unroll
        for (int k = 0; k < 4; k++){
            float s = dot64(pb[k & 1] + half * 64, Ereg);
            s += __shfl_xor_sync(0xffffffffu, s, 1);     // combine halves (bitwise identical on both lanes)
            float u = __expf(lgbuf[k]);                  // pad labels: exp(-1e30) -> 0
            float v = s * u;
            if (k == 0) v *= pend;
            if (k == 3){
                float mw = v;
                #pragma unroll
                for (int o = 2; o <= 16; o <<= 1)
                    mw = fmaxf(mw, __shfl_xor_sync(0xffffffffu, mw, o));
                if (lane == 0) red[wrp] = mw;
            }
            if (!half) pb[(k & 1) ^ 1][label] = v;
            GBAR(barid);
            if (k == 3){
                const float4* r4 = (const float4*)red;
                float4 ra = r4[0], rb = r4[1];
                float m = fmaxf(fmaxf(fmaxf(ra.x, ra.y), fmaxf(ra.z, ra.w)),
                                fmaxf(fmaxf(rb.x, rb.y), fmaxf(rb.z, rb.w)));
                pend = __fdividef(1.f, m);
                c += __logf(m);
            }
        }
        #pragma unroll
        for (int k = 0; k < 4; k++) lgbuf[k] = nbuf[k];
        t0 += 4;
    }

    // ---- remainder (0..3 steps), renorm every step ----
    int rem = len - t0;
    #pragma unroll
    for (int k = 0; k < 3; k++){
        if (k < rem){
            float s = dot64(pb[k & 1] + half * 64, Ereg);
            s += __shfl_xor_sync(0xffffffffu, s, 1);
            float u = __expf(lgbuf[k]);
            float v = s * u * pend;
            float mw = v;
            #pragma unroll
            for (int o = 2; o <= 16; o <<= 1)
                mw = fmaxf(mw, __shfl_xor_sync(0xffffffffu, mw, o));
            if (lane == 0) red[wrp] = mw;
            if (!half) pb[(k & 1) ^ 1][label] = v;
            GBAR(barid);
            const float4* r4 = (const float4*)red;
            float4 ra = r4[0], rb = r4[1];
            float m = fmaxf(fmaxf(fmaxf(ra.x, ra.y), fmaxf(ra.z, ra.w)),
                            fmaxf(fmaxf(rb.x, rb.y), fmaxf(rb.z, rb.w)));
            pend = __fdividef(1.f, m);
            c += __logf(m);
        }
    }

    // ---- epilogue ----
    GBAR(barid);   // protect red[] of last renorm from epilogue writes
    const float* pcur = pb[rem & 1];
    float term = (!half) ? pcur[label] * __expf(trans[(L_ - 1) * L_ + label]) : 0.f;
    #pragma unroll
    for (int o = 16; o; o >>= 1){
        term  += __shfl_xor_sync(0xffffffffu, term,  o);
        gpart += __shfl_xor_sync(0xffffffffu, gpart, o);
    }
    if (lane == 0){ red[wrp] = term; red[8 + wrp] = gpart; }
    GBAR(barid);
    if (gt == 0){
        float S = red[0] + red[1] + red[2] + red[3] + red[4] + red[5] + red[6] + red[7];
        float G = red[8] + red[9] + red[10] + red[11] + red[12] + red[13] + red[14] + red[15];
        out[seq] = G - (c + __logf(S * pend));
    }
}

extern "C" void kernel_launch(void* const* d_in, const int* in_sizes, int n_in,
                              void* d_out, int out_size)
{
    (void)in_sizes; (void)n_in; (void)out_size;
    const float* logits = (const float*)d_in[0];
    const int*   labels = (const int*)d_in[1];
    const int*   lens   = (const int*)d_in[2];
    const float* trans  = (const float*)d_in[3];
    float*       out    = (float*)d_out;

    crf_sort_kernel<<<1, B_>>>(lens);
    crf_main_kernel<<<B_ / 2, 512>>>(logits, labels, lens, trans, out);
}